// round 2
// baseline (speedup 1.0000x reference)
#include <cuda_runtime.h>
#include <cstdint>

#define C 256
#define MAXN 100000
#define KTOT 512   // stacked K dimension: [ax | h0]

// Scratch (allocation-free rule: __device__ globals)
__device__ float g_ax[(size_t)MAXN * C];   // A @ x accumulator, ~100 MB
__device__ float g_M[KTOT * C];            // stacked blend matrix [M1; M2], 512 KB
__device__ int   g_is64;                   // 1 if edge_index buffer is int64

// ---------------------------------------------------------------------------
// Detect edge-index dtype: for little-endian int64 (non-negative indices),
// every odd int32 word is the zero high-half. For int32 data, odd words are
// random node indices (essentially never all zero over 512 samples).
// ---------------------------------------------------------------------------
__global__ void detect_idx_kernel(const int* __restrict__ ei32, int nwords) {
    if (threadIdx.x != 0 || blockIdx.x != 0) return;
    int nonzero_odd = 0;
    int lim = nwords < 1024 ? nwords : 1024;
    for (int i = 1; i < lim; i += 2) nonzero_odd += (ei32[i] != 0);
    g_is64 = (nonzero_odd == 0) ? 1 : 0;
}

// ---------------------------------------------------------------------------
// Zero the SpMM accumulator
// ---------------------------------------------------------------------------
__global__ void zero_ax_kernel(int total_f4) {
    float4* p = reinterpret_cast<float4*>(g_ax);
    float4 z = make_float4(0.f, 0.f, 0.f, 0.f);
    for (int i = blockIdx.x * blockDim.x + threadIdx.x; i < total_f4;
         i += gridDim.x * blockDim.x)
        p[i] = z;
}

// ---------------------------------------------------------------------------
// Build blended weight matrix:
//   rows [0,256):   M1[k,n] = (1-a)*( (1-b)*I + b*W1 )[k,n]
//   rows [256,512): M2[k,n] =   a  *( (1-b)*I + b*W2 )[k,n]
// so that out = ax @ M1 + h0 @ M2 = [ax|h0] @ g_M
// ---------------------------------------------------------------------------
__global__ void build_M_kernel(const float* __restrict__ W1,
                               const float* __restrict__ W2,
                               const float* __restrict__ p_alpha,
                               const float* __restrict__ p_beta) {
    float a = *p_alpha, b = *p_beta;
    float c1 = (1.f - a) * (1.f - b);   // diag for M1
    float c2 = (1.f - a) * b;           // W1 scale
    float c3 = a * (1.f - b);           // diag for M2
    float c4 = a * b;                   // W2 scale
    int i = blockIdx.x * blockDim.x + threadIdx.x;
    if (i >= KTOT * C) return;
    int k = i / C, n = i % C;
    float v;
    if (k < C) {
        v = c2 * W1[k * C + n] + (k == n ? c1 : 0.f);
    } else {
        int k2 = k - C;
        v = c4 * W2[k2 * C + n] + (k2 == n ? c3 : 0.f);
    }
    g_M[i] = v;
}

// ---------------------------------------------------------------------------
// SpMM: one warp per edge. g_ax[row] += val * x[col]
// Vectorized reduction atomics (red.global.add.v4.f32, sm_90+).
// ---------------------------------------------------------------------------
__device__ __forceinline__ void red_add_v4(float* p, float4 v) {
    asm volatile("red.global.add.v4.f32 [%0], {%1, %2, %3, %4};"
                 :: "l"(p), "f"(v.x), "f"(v.y), "f"(v.z), "f"(v.w)
                 : "memory");
}

__global__ void spmm_kernel(const float* __restrict__ x,
                            const float* __restrict__ vals,
                            const void* __restrict__ ei_raw,
                            int E, int N) {
    const int is64 = g_is64;
    int gw   = (blockIdx.x * blockDim.x + threadIdx.x) >> 5;
    int lane = threadIdx.x & 31;
    int nw   = (gridDim.x * blockDim.x) >> 5;
    const long long* ei64 = (const long long*)ei_raw;
    const int*       ei32 = (const int*)ei_raw;

    for (int e = gw; e < E; e += nw) {
        int row, col;
        if (is64) {
            row = (int)__ldg(&ei64[e]);
            col = (int)__ldg(&ei64[(size_t)E + e]);
        } else {
            row = __ldg(&ei32[e]);
            col = __ldg(&ei32[(size_t)E + e]);
        }
        // defensive: never fault — wrong-hypothesis turns into rel_err signal
        if ((unsigned)row >= (unsigned)N || (unsigned)col >= (unsigned)N) continue;
        float v = __ldg(&vals[e]);

        const float4* xr = reinterpret_cast<const float4*>(x + (size_t)col * C);
        float4 a = __ldg(&xr[lane]);
        float4 b = __ldg(&xr[lane + 32]);
        a.x *= v; a.y *= v; a.z *= v; a.w *= v;
        b.x *= v; b.y *= v; b.z *= v; b.w *= v;

        float* dst = g_ax + (size_t)row * C;
        red_add_v4(dst + lane * 4, a);
        red_add_v4(dst + 128 + lane * 4, b);
    }
}

// ---------------------------------------------------------------------------
// SGEMM: out[N,256] = Avirt[N,512] @ g_M[512,256]
//   Avirt(r, k) = k < 256 ? g_ax[r,k] : h0[r,k-256]
// Tile 128x128, BK=16, 256 threads, 2x2 quadrant micro-tile (8x8 per thread).
// ---------------------------------------------------------------------------
#define BM 128
#define BN 128
#define BK 16

__global__ __launch_bounds__(256, 2)
void gemm_kernel(const float* __restrict__ h0, float* __restrict__ out, int N) {
    __shared__ float As[BK][BM];   // transposed A tile: As[k][m]
    __shared__ float Bs[BK][BN];   // natural B tile:    Bs[k][n]

    const int bm = blockIdx.x * BM;
    const int bn = blockIdx.y * BN;
    const int tid = threadIdx.x;
    const int tx = tid & 15;       // 0..15  -> column quadrants
    const int ty = tid >> 4;       // 0..15  -> row quadrants

    float acc[8][8];
    #pragma unroll
    for (int i = 0; i < 8; i++)
        #pragma unroll
        for (int j = 0; j < 8; j++) acc[i][j] = 0.f;

    for (int kt = 0; kt < KTOT; kt += BK) {
        // ---- stage A tile: 128 rows x 16 cols (2 float4 loads / thread) ----
        const float* Abase = (kt < C) ? (g_ax + kt) : (h0 + (kt - C));
        #pragma unroll
        for (int t = tid; t < 512; t += 256) {
            int row = t >> 2;            // 0..127
            int c4  = (t & 3) * 4;       // 0,4,8,12
            int grow = bm + row;
            float4 v = make_float4(0.f, 0.f, 0.f, 0.f);
            if (grow < N)
                v = *reinterpret_cast<const float4*>(Abase + (size_t)grow * C + c4);
            As[c4 + 0][row] = v.x;
            As[c4 + 1][row] = v.y;
            As[c4 + 2][row] = v.z;
            As[c4 + 3][row] = v.w;
        }
        // ---- stage B tile: 16 rows x 128 cols ----
        #pragma unroll
        for (int t = tid; t < 512; t += 256) {
            int row = t >> 5;            // 0..15
            int c4  = (t & 31) * 4;      // 0..124
            float4 v = *reinterpret_cast<const float4*>(
                g_M + (size_t)(kt + row) * C + bn + c4);
            *reinterpret_cast<float4*>(&Bs[row][c4]) = v;
        }
        __syncthreads();

        // ---- 8x8 micro-tile over the 2x2 quadrants ----
        #pragma unroll
        for (int k = 0; k < BK; k++) {
            float ar[8], br[8];
            float4 a0 = *reinterpret_cast<const float4*>(&As[k][ty * 4]);
            float4 a1 = *reinterpret_cast<const float4*>(&As[k][64 + ty * 4]);
            float4 b0 = *reinterpret_cast<const float4*>(&Bs[k][tx * 4]);
            float4 b1 = *reinterpret_cast<const float4*>(&Bs[k][64 + tx * 4]);
            ar[0]=a0.x; ar[1]=a0.y; ar[2]=a0.z; ar[3]=a0.w;
            ar[4]=a1.x; ar[5]=a1.y; ar[6]=a1.z; ar[7]=a1.w;
            br[0]=b0.x; br[1]=b0.y; br[2]=b0.z; br[3]=b0.w;
            br[4]=b1.x; br[5]=b1.y; br[6]=b1.z; br[7]=b1.w;
            #pragma unroll
            for (int i = 0; i < 8; i++)
                #pragma unroll
                for (int j = 0; j < 8; j++)
                    acc[i][j] += ar[i] * br[j];
        }
        __syncthreads();
    }

    // ---- epilogue: write 2x2 quadrants of 4x4 float4 blocks ----
    #pragma unroll
    for (int qi = 0; qi < 2; qi++) {
        #pragma unroll
        for (int ii = 0; ii < 4; ii++) {
            int grow = bm + qi * 64 + ty * 4 + ii;
            if (grow >= N) continue;
            int ai = qi * 4 + ii;
            float* orow = out + (size_t)grow * C + bn;
            *reinterpret_cast<float4*>(orow + tx * 4) =
                make_float4(acc[ai][0], acc[ai][1], acc[ai][2], acc[ai][3]);
            *reinterpret_cast<float4*>(orow + 64 + tx * 4) =
                make_float4(acc[ai][4], acc[ai][5], acc[ai][6], acc[ai][7]);
        }
    }
}

// ---------------------------------------------------------------------------
// Launch
// ---------------------------------------------------------------------------
extern "C" void kernel_launch(void* const* d_in, const int* in_sizes, int n_in,
                              void* d_out, int out_size) {
    const float* x    = (const float*)d_in[0];
    const float* vals = (const float*)d_in[1];
    const void*  ei   = d_in[2];
    const float* h0   = (const float*)d_in[3];
    const float* W1   = (const float*)d_in[4];
    const float* W2   = (const float*)d_in[5];
    const float* pa   = (const float*)d_in[6];
    const float* pb   = (const float*)d_in[7];
    float* out = (float*)d_out;

    const int N = in_sizes[0] / C;     // 100000
    const int E = in_sizes[1];         // 3200000

    // 0) detect int32 vs int64 edge buffer (graph-capturable, deterministic)
    detect_idx_kernel<<<1, 32>>>((const int*)ei, in_sizes[2]);

    // 1) zero accumulator
    int total_f4 = (N * C) / 4;
    zero_ax_kernel<<<2048, 256>>>(total_f4);

    // 2) build blended [M1;M2]
    build_M_kernel<<<(KTOT * C + 255) / 256, 256>>>(W1, W2, pa, pb);

    // 3) SpMM (one warp per edge, 8 warps per block)
    int spmm_blocks = (E + 7) / 8;
    if (spmm_blocks > 80000) spmm_blocks = 80000;   // grid-stride
    spmm_kernel<<<spmm_blocks, 256>>>(x, vals, ei, E, N);

    // 4) fused GEMM: out = [ax|h0] @ g_M
    dim3 grid((N + BM - 1) / BM, C / BN);
    gemm_kernel<<<grid, 256>>>(h0, out, N);
}

// round 3
// speedup vs baseline: 1.3384x; 1.3384x over previous
#include <cuda_runtime.h>
#include <cstdint>

#define C 256
#define MAXN 100000
#define MAXE 3200000
#define KTOT 512   // stacked K dimension: [ax | h0]

// Scratch (allocation-free rule: __device__ globals)
__device__ float g_ax[(size_t)MAXN * C];   // A @ x result, ~100 MB
__device__ float g_M[KTOT * C];            // stacked blend matrix [M1; M2]
__device__ int   g_is64;                   // 1 if edge_index buffer is int64
__device__ int   g_cnt[MAXN];              // per-row edge counts
__device__ int   g_rowstart[MAXN + 1];     // CSR offsets
__device__ int   g_cursor[MAXN];           // scatter tickets
__device__ int   g_cols[MAXE];             // CSR column indices
__device__ float g_vals[MAXE];             // CSR values

// ---------------------------------------------------------------------------
// Detect edge-index dtype (int64 => all odd int32 words are zero high-halves)
// ---------------------------------------------------------------------------
__global__ void detect_idx_kernel(const int* __restrict__ ei32, int nwords) {
    if (threadIdx.x != 0 || blockIdx.x != 0) return;
    int nonzero_odd = 0;
    int lim = nwords < 1024 ? nwords : 1024;
    for (int i = 1; i < lim; i += 2) nonzero_odd += (ei32[i] != 0);
    g_is64 = (nonzero_odd == 0) ? 1 : 0;
}

__global__ void zero_cnt_kernel(int N) {
    int i = blockIdx.x * blockDim.x + threadIdx.x;
    if (i < N) g_cnt[i] = 0;
}

// ---------------------------------------------------------------------------
// Build blended weight matrix [M1; M2] so out = [ax|h0] @ g_M
// ---------------------------------------------------------------------------
__global__ void build_M_kernel(const float* __restrict__ W1,
                               const float* __restrict__ W2,
                               const float* __restrict__ p_alpha,
                               const float* __restrict__ p_beta) {
    float a = *p_alpha, b = *p_beta;
    float c1 = (1.f - a) * (1.f - b);
    float c2 = (1.f - a) * b;
    float c3 = a * (1.f - b);
    float c4 = a * b;
    int i = blockIdx.x * blockDim.x + threadIdx.x;
    if (i >= KTOT * C) return;
    int k = i / C, n = i % C;
    float v;
    if (k < C) {
        v = c2 * W1[k * C + n] + (k == n ? c1 : 0.f);
    } else {
        int k2 = k - C;
        v = c4 * W2[k2 * C + n] + (k2 == n ? c3 : 0.f);
    }
    g_M[i] = v;
}

// ---------------------------------------------------------------------------
// CSR build: histogram -> scan -> ticket scatter
// ---------------------------------------------------------------------------
__global__ void hist_kernel(const void* __restrict__ ei_raw, int E, int N) {
    const int is64 = g_is64;
    const long long* ei64 = (const long long*)ei_raw;
    const int*       ei32 = (const int*)ei_raw;
    for (int e = blockIdx.x * blockDim.x + threadIdx.x; e < E;
         e += gridDim.x * blockDim.x) {
        int row = is64 ? (int)__ldg(&ei64[e]) : __ldg(&ei32[e]);
        if ((unsigned)row < (unsigned)N) atomicAdd(&g_cnt[row], 1);
    }
}

__global__ void scan_kernel(int N, int E) {
    __shared__ int part[1024];
    const int t = threadIdx.x;
    const int chunk = (N + 1023) / 1024;
    const int start = t * chunk;
    const int end   = min(start + chunk, N);
    int s = 0;
    for (int i = start; i < end; i++) s += g_cnt[i];
    part[t] = s;
    __syncthreads();
    // inclusive scan (Hillis-Steele)
    for (int off = 1; off < 1024; off <<= 1) {
        int add = (t >= off) ? part[t - off] : 0;
        __syncthreads();
        part[t] += add;
        __syncthreads();
    }
    int base = part[t] - s;   // exclusive prefix of this chunk
    for (int i = start; i < end; i++) {
        int c = g_cnt[i];
        g_rowstart[i] = base;
        g_cursor[i]   = base;
        base += c;
    }
    if (t == 0) g_rowstart[N] = E;
}

__global__ void scatter_kernel(const void* __restrict__ ei_raw,
                               const float* __restrict__ vals, int E, int N) {
    const int is64 = g_is64;
    const long long* ei64 = (const long long*)ei_raw;
    const int*       ei32 = (const int*)ei_raw;
    for (int e = blockIdx.x * blockDim.x + threadIdx.x; e < E;
         e += gridDim.x * blockDim.x) {
        int row, col;
        if (is64) {
            row = (int)__ldg(&ei64[e]);
            col = (int)__ldg(&ei64[(size_t)E + e]);
        } else {
            row = __ldg(&ei32[e]);
            col = __ldg(&ei32[(size_t)E + e]);
        }
        if ((unsigned)row >= (unsigned)N || (unsigned)col >= (unsigned)N) continue;
        int pos = atomicAdd(&g_cursor[row], 1);
        g_cols[pos] = col;
        g_vals[pos] = __ldg(&vals[e]);
    }
}

// ---------------------------------------------------------------------------
// SpMM over CSR: one warp per row, register accumulation, no float atomics.
// Streaming store of g_ax keeps x L2-resident.
// ---------------------------------------------------------------------------
__global__ __launch_bounds__(256)
void spmm_csr_kernel(const float* __restrict__ x, int N) {
    int warp = (blockIdx.x * blockDim.x + threadIdx.x) >> 5;
    int lane = threadIdx.x & 31;
    int nw   = (gridDim.x * blockDim.x) >> 5;
    for (int r = warp; r < N; r += nw) {
        int s = g_rowstart[r];
        int e = g_rowstart[r + 1];
        float4 acc0 = make_float4(0.f, 0.f, 0.f, 0.f);
        float4 acc1 = make_float4(0.f, 0.f, 0.f, 0.f);
        #pragma unroll 2
        for (int i = s; i < e; i++) {
            int col  = __ldg(&g_cols[i]);     // warp-uniform broadcast
            float v  = __ldg(&g_vals[i]);
            const float4* xr = reinterpret_cast<const float4*>(x + (size_t)col * C);
            float4 a = __ldg(&xr[lane]);
            float4 b = __ldg(&xr[lane + 32]);
            acc0.x += v * a.x; acc0.y += v * a.y;
            acc0.z += v * a.z; acc0.w += v * a.w;
            acc1.x += v * b.x; acc1.y += v * b.y;
            acc1.z += v * b.z; acc1.w += v * b.w;
        }
        float4* dst = reinterpret_cast<float4*>(g_ax + (size_t)r * C);
        __stcs(&dst[lane], acc0);
        __stcs(&dst[lane + 32], acc1);
    }
}

// ---------------------------------------------------------------------------
// SGEMM: out[N,256] = [ax|h0] @ g_M[512,256]
// Tile 128x128, BK=16, 256 threads, 2x2 quadrant micro-tile (8x8 per thread).
// ---------------------------------------------------------------------------
#define BM 128
#define BN 128
#define BK 16

__global__ __launch_bounds__(256, 2)
void gemm_kernel(const float* __restrict__ h0, float* __restrict__ out, int N) {
    __shared__ float As[BK][BM];
    __shared__ float Bs[BK][BN];

    const int bm = blockIdx.x * BM;
    const int bn = blockIdx.y * BN;
    const int tid = threadIdx.x;
    const int tx = tid & 15;
    const int ty = tid >> 4;

    float acc[8][8];
    #pragma unroll
    for (int i = 0; i < 8; i++)
        #pragma unroll
        for (int j = 0; j < 8; j++) acc[i][j] = 0.f;

    for (int kt = 0; kt < KTOT; kt += BK) {
        const float* Abase = (kt < C) ? (g_ax + kt) : (h0 + (kt - C));
        #pragma unroll
        for (int t = tid; t < 512; t += 256) {
            int row = t >> 2;
            int c4  = (t & 3) * 4;
            int grow = bm + row;
            float4 v = make_float4(0.f, 0.f, 0.f, 0.f);
            if (grow < N)
                v = *reinterpret_cast<const float4*>(Abase + (size_t)grow * C + c4);
            As[c4 + 0][row] = v.x;
            As[c4 + 1][row] = v.y;
            As[c4 + 2][row] = v.z;
            As[c4 + 3][row] = v.w;
        }
        #pragma unroll
        for (int t = tid; t < 512; t += 256) {
            int row = t >> 5;
            int c4  = (t & 31) * 4;
            float4 v = *reinterpret_cast<const float4*>(
                g_M + (size_t)(kt + row) * C + bn + c4);
            *reinterpret_cast<float4*>(&Bs[row][c4]) = v;
        }
        __syncthreads();

        #pragma unroll
        for (int k = 0; k < BK; k++) {
            float ar[8], br[8];
            float4 a0 = *reinterpret_cast<const float4*>(&As[k][ty * 4]);
            float4 a1 = *reinterpret_cast<const float4*>(&As[k][64 + ty * 4]);
            float4 b0 = *reinterpret_cast<const float4*>(&Bs[k][tx * 4]);
            float4 b1 = *reinterpret_cast<const float4*>(&Bs[k][64 + tx * 4]);
            ar[0]=a0.x; ar[1]=a0.y; ar[2]=a0.z; ar[3]=a0.w;
            ar[4]=a1.x; ar[5]=a1.y; ar[6]=a1.z; ar[7]=a1.w;
            br[0]=b0.x; br[1]=b0.y; br[2]=b0.z; br[3]=b0.w;
            br[4]=b1.x; br[5]=b1.y; br[6]=b1.z; br[7]=b1.w;
            #pragma unroll
            for (int i = 0; i < 8; i++)
                #pragma unroll
                for (int j = 0; j < 8; j++)
                    acc[i][j] += ar[i] * br[j];
        }
        __syncthreads();
    }

    #pragma unroll
    for (int qi = 0; qi < 2; qi++) {
        #pragma unroll
        for (int ii = 0; ii < 4; ii++) {
            int grow = bm + qi * 64 + ty * 4 + ii;
            if (grow >= N) continue;
            int ai = qi * 4 + ii;
            float* orow = out + (size_t)grow * C + bn;
            *reinterpret_cast<float4*>(orow + tx * 4) =
                make_float4(acc[ai][0], acc[ai][1], acc[ai][2], acc[ai][3]);
            *reinterpret_cast<float4*>(orow + 64 + tx * 4) =
                make_float4(acc[ai][4], acc[ai][5], acc[ai][6], acc[ai][7]);
        }
    }
}

// ---------------------------------------------------------------------------
// Launch
// ---------------------------------------------------------------------------
extern "C" void kernel_launch(void* const* d_in, const int* in_sizes, int n_in,
                              void* d_out, int out_size) {
    const float* x    = (const float*)d_in[0];
    const float* vals = (const float*)d_in[1];
    const void*  ei   = d_in[2];
    const float* h0   = (const float*)d_in[3];
    const float* W1   = (const float*)d_in[4];
    const float* W2   = (const float*)d_in[5];
    const float* pa   = (const float*)d_in[6];
    const float* pb   = (const float*)d_in[7];
    float* out = (float*)d_out;

    const int N = in_sizes[0] / C;     // 100000
    int E = in_sizes[1];               // 3200000
    if (E > MAXE) E = MAXE;

    // 0) detect int32 vs int64 edge buffer
    detect_idx_kernel<<<1, 32>>>((const int*)ei, in_sizes[2]);

    // 1) build blended [M1;M2]
    build_M_kernel<<<(KTOT * C + 255) / 256, 256>>>(W1, W2, pa, pb);

    // 2) CSR build
    zero_cnt_kernel<<<(N + 255) / 256, 256>>>(N);
    hist_kernel<<<4096, 256>>>(ei, E, N);
    scan_kernel<<<1, 1024>>>(N, E);
    scatter_kernel<<<4096, 256>>>(ei, vals, E, N);

    // 3) SpMM over CSR (one warp per row)
    int spmm_blocks = (N * 32 + 255) / 256;
    spmm_csr_kernel<<<spmm_blocks, 256>>>(x, N);

    // 4) fused GEMM: out = [ax|h0] @ g_M
    dim3 grid((N + BM - 1) / BM, C / BN);
    gemm_kernel<<<grid, 256>>>(h0, out, N);
}

// round 4
// speedup vs baseline: 2.0345x; 1.5201x over previous
#include <cuda_runtime.h>
#include <cuda_bf16.h>
#include <cstdint>

#define C 256
#define MAXN 100000
#define MAXE 3200000
#define KTOT 512   // stacked K dimension: [ax | h0]

// Scratch (allocation-free rule: __device__ globals)
__device__ float g_ax[(size_t)MAXN * C];          // A @ x result, ~100 MB
__device__ __nv_bfloat16 g_MtH[C * KTOT];         // M^T hi, [n][k]
__device__ __nv_bfloat16 g_MtL[C * KTOT];         // M^T lo, [n][k]
__device__ int   g_is64;
__device__ int   g_cnt[MAXN];
__device__ int   g_rowstart[MAXN + 1];
__device__ int   g_cursor[MAXN];
__device__ int   g_cols[MAXE];
__device__ float g_vals[MAXE];

// ---------------------------------------------------------------------------
// Detect edge-index dtype (int64 => all odd int32 words are zero high-halves)
// ---------------------------------------------------------------------------
__global__ void detect_idx_kernel(const int* __restrict__ ei32, int nwords) {
    if (threadIdx.x != 0 || blockIdx.x != 0) return;
    int nonzero_odd = 0;
    int lim = nwords < 1024 ? nwords : 1024;
    for (int i = 1; i < lim; i += 2) nonzero_odd += (ei32[i] != 0);
    g_is64 = (nonzero_odd == 0) ? 1 : 0;
}

__global__ void zero_cnt_kernel(int N) {
    int i = blockIdx.x * blockDim.x + threadIdx.x;
    if (i < N) g_cnt[i] = 0;
}

// ---------------------------------------------------------------------------
// Build transposed+split blend matrix: g_Mt[n][k] (hi/lo bf16), where
//   k<256:  M[k][n] = (1-a)*b*W1[k][n] + (k==n)*(1-a)*(1-b)
//   k>=256: M[k][n] =   a  *b*W2[k'][n] + (k'==n)*a*(1-b)
// so out = [ax|h0] @ M, with B read n-major for ldmatrix.
// ---------------------------------------------------------------------------
__global__ void build_Mt_kernel(const float* __restrict__ W1,
                                const float* __restrict__ W2,
                                const float* __restrict__ p_alpha,
                                const float* __restrict__ p_beta) {
    float a = *p_alpha, b = *p_beta;
    float c1 = (1.f - a) * (1.f - b);
    float c2 = (1.f - a) * b;
    float c3 = a * (1.f - b);
    float c4 = a * b;
    int i = blockIdx.x * blockDim.x + threadIdx.x;
    if (i >= C * KTOT) return;
    int n = i / KTOT, k = i % KTOT;
    float v;
    if (k < C) {
        v = c2 * W1[k * C + n] + (k == n ? c1 : 0.f);
    } else {
        int k2 = k - C;
        v = c4 * W2[k2 * C + n] + (k2 == n ? c3 : 0.f);
    }
    __nv_bfloat16 hi = __float2bfloat16_rn(v);
    float residual = v - __bfloat162float(hi);
    g_MtH[i] = hi;
    g_MtL[i] = __float2bfloat16_rn(residual);
}

// ---------------------------------------------------------------------------
// CSR build: histogram -> scan -> ticket scatter
// ---------------------------------------------------------------------------
__global__ void hist_kernel(const void* __restrict__ ei_raw, int E, int N) {
    const int is64 = g_is64;
    const long long* ei64 = (const long long*)ei_raw;
    const int*       ei32 = (const int*)ei_raw;
    for (int e = blockIdx.x * blockDim.x + threadIdx.x; e < E;
         e += gridDim.x * blockDim.x) {
        int row = is64 ? (int)__ldg(&ei64[e]) : __ldg(&ei32[e]);
        if ((unsigned)row < (unsigned)N) atomicAdd(&g_cnt[row], 1);
    }
}

__global__ void scan_kernel(int N, int E) {
    __shared__ int part[1024];
    const int t = threadIdx.x;
    const int chunk = (N + 1023) / 1024;
    const int start = t * chunk;
    const int end   = min(start + chunk, N);
    int s = 0;
    for (int i = start; i < end; i++) s += g_cnt[i];
    part[t] = s;
    __syncthreads();
    for (int off = 1; off < 1024; off <<= 1) {
        int add = (t >= off) ? part[t - off] : 0;
        __syncthreads();
        part[t] += add;
        __syncthreads();
    }
    int base = part[t] - s;
    for (int i = start; i < end; i++) {
        int c = g_cnt[i];
        g_rowstart[i] = base;
        g_cursor[i]   = base;
        base += c;
    }
    if (t == 0) g_rowstart[N] = E;
}

__global__ void scatter_kernel(const void* __restrict__ ei_raw,
                               const float* __restrict__ vals, int E, int N) {
    const int is64 = g_is64;
    const long long* ei64 = (const long long*)ei_raw;
    const int*       ei32 = (const int*)ei_raw;
    for (int e = blockIdx.x * blockDim.x + threadIdx.x; e < E;
         e += gridDim.x * blockDim.x) {
        int row, col;
        if (is64) {
            row = (int)__ldg(&ei64[e]);
            col = (int)__ldg(&ei64[(size_t)E + e]);
        } else {
            row = __ldg(&ei32[e]);
            col = __ldg(&ei32[(size_t)E + e]);
        }
        if ((unsigned)row >= (unsigned)N || (unsigned)col >= (unsigned)N) continue;
        int pos = atomicAdd(&g_cursor[row], 1);
        g_cols[pos] = col;
        g_vals[pos] = __ldg(&vals[e]);
    }
}

// ---------------------------------------------------------------------------
// SpMM over CSR: one warp per row, register accumulation, no float atomics.
// ---------------------------------------------------------------------------
__global__ __launch_bounds__(256)
void spmm_csr_kernel(const float* __restrict__ x, int N) {
    int warp = (blockIdx.x * blockDim.x + threadIdx.x) >> 5;
    int lane = threadIdx.x & 31;
    int nw   = (gridDim.x * blockDim.x) >> 5;
    for (int r = warp; r < N; r += nw) {
        int s = g_rowstart[r];
        int e = g_rowstart[r + 1];
        float4 acc0 = make_float4(0.f, 0.f, 0.f, 0.f);
        float4 acc1 = make_float4(0.f, 0.f, 0.f, 0.f);
        #pragma unroll 2
        for (int i = s; i < e; i++) {
            int col  = __ldg(&g_cols[i]);
            float v  = __ldg(&g_vals[i]);
            const float4* xr = reinterpret_cast<const float4*>(x + (size_t)col * C);
            float4 a = __ldg(&xr[lane]);
            float4 b = __ldg(&xr[lane + 32]);
            acc0.x += v * a.x; acc0.y += v * a.y;
            acc0.z += v * a.z; acc0.w += v * a.w;
            acc1.x += v * b.x; acc1.y += v * b.y;
            acc1.z += v * b.z; acc1.w += v * b.w;
        }
        float4* dst = reinterpret_cast<float4*>(g_ax + (size_t)r * C);
        __stcs(&dst[lane], acc0);
        __stcs(&dst[lane + 32], acc1);
    }
}

// ---------------------------------------------------------------------------
// Tensor-core GEMM: out[N,256] = [ax|h0] @ M, bf16 hi/lo split (fp32-accurate)
//   out = Ahi*Bhi + Ahi*Blo + Alo*Bhi  (fp32 accumulate)
// CTA tile 128x128, BK=32, 8 warps of 32x64, mma.m16n8k16, ldmatrix loads.
// ---------------------------------------------------------------------------
#define BM 128
#define BN 128
#define BK 32
#define LDS_W 20   // uint32 words per smem row: 16 data + 4 pad (conflict-free)

__device__ __forceinline__ uint32_t s2u(const void* p) {
    uint32_t a;
    asm("{ .reg .u64 t; cvta.to.shared.u64 t, %1; cvt.u32.u64 %0, t; }"
        : "=r"(a) : "l"(p));
    return a;
}

__device__ __forceinline__ void ldm_x4(uint32_t* r, uint32_t addr) {
    asm volatile("ldmatrix.sync.aligned.m8n8.x4.shared.b16 {%0,%1,%2,%3}, [%4];"
                 : "=r"(r[0]), "=r"(r[1]), "=r"(r[2]), "=r"(r[3]) : "r"(addr));
}

__device__ __forceinline__ void mma_bf16(float* c, const uint32_t* a,
                                         uint32_t b0, uint32_t b1) {
    asm volatile(
        "mma.sync.aligned.m16n8k16.row.col.f32.bf16.bf16.f32 "
        "{%0,%1,%2,%3}, {%4,%5,%6,%7}, {%8,%9}, {%0,%1,%2,%3};"
        : "+f"(c[0]), "+f"(c[1]), "+f"(c[2]), "+f"(c[3])
        : "r"(a[0]), "r"(a[1]), "r"(a[2]), "r"(a[3]), "r"(b0), "r"(b1));
}

__device__ __forceinline__ void split_pair(float x, float y,
                                           uint32_t& hi, uint32_t& lo) {
    __nv_bfloat162 h = __floats2bfloat162_rn(x, y);
    float hx = __bfloat162float(__low2bfloat16(h));
    float hy = __bfloat162float(__high2bfloat16(h));
    __nv_bfloat162 l = __floats2bfloat162_rn(x - hx, y - hy);
    hi = *reinterpret_cast<uint32_t*>(&h);
    lo = *reinterpret_cast<uint32_t*>(&l);
}

__global__ __launch_bounds__(256)
void gemm_bf16_kernel(const float* __restrict__ h0, float* __restrict__ out, int N) {
    __shared__ uint32_t AsH[BM * LDS_W], AsL[BM * LDS_W];
    __shared__ uint32_t BsH[BN * LDS_W], BsL[BN * LDS_W];

    const int tid  = threadIdx.x;
    const int lane = tid & 31;
    const int wid  = tid >> 5;
    const int warp_m = (wid & 3) * 32;
    const int warp_n = (wid >> 2) * 64;
    const int bm = blockIdx.x * BM;
    const int bn = blockIdx.y * BN;

    // ldmatrix lane->address components
    const int a_row = (lane & 7) + ((lane >> 3) & 1) * 8;  // within 16-row A tile
    const int a_k   = (lane >> 4) * 8;                     // bf16 col offset
    const int b_row = (lane & 7) + (lane >> 4) * 8;        // within 16-row B pair
    const int b_k   = ((lane >> 3) & 1) * 8;

    const uint32_t asH = s2u(AsH), asL = s2u(AsL);
    const uint32_t bsH = s2u(BsH), bsL = s2u(BsL);

    float acc[2][8][4];
    #pragma unroll
    for (int i = 0; i < 2; i++)
        #pragma unroll
        for (int j = 0; j < 8; j++)
            #pragma unroll
            for (int q = 0; q < 4; q++) acc[i][j][q] = 0.f;

    // loader mapping: thread -> (row, 16-wide k group)
    const int lrow = tid >> 1;
    const int lkg  = (tid & 1) * 16;

    for (int kt = 0; kt < KTOT; kt += BK) {
        // ---- stage A tile (fp32 -> bf16 hi/lo) ----
        const float* Abase = (kt < C) ? (g_ax + kt) : (h0 + (kt - C));
        {
            int grow = bm + lrow;
            float4 v0 = make_float4(0.f,0.f,0.f,0.f), v1 = v0, v2 = v0, v3 = v0;
            if (grow < N) {
                const float4* p = reinterpret_cast<const float4*>(
                    Abase + (size_t)grow * C + lkg);
                v0 = p[0]; v1 = p[1]; v2 = p[2]; v3 = p[3];
            }
            uint32_t* dH = AsH + lrow * LDS_W + (lkg >> 1);
            uint32_t* dL = AsL + lrow * LDS_W + (lkg >> 1);
            split_pair(v0.x, v0.y, dH[0], dL[0]);
            split_pair(v0.z, v0.w, dH[1], dL[1]);
            split_pair(v1.x, v1.y, dH[2], dL[2]);
            split_pair(v1.z, v1.w, dH[3], dL[3]);
            split_pair(v2.x, v2.y, dH[4], dL[4]);
            split_pair(v2.z, v2.w, dH[5], dL[5]);
            split_pair(v3.x, v3.y, dH[6], dL[6]);
            split_pair(v3.z, v3.w, dH[7], dL[7]);
        }
        // ---- stage B tile (pre-split, n-major; direct copy) ----
        {
            const uint4* pH = reinterpret_cast<const uint4*>(
                g_MtH + (size_t)(bn + lrow) * KTOT + kt + lkg);
            const uint4* pL = reinterpret_cast<const uint4*>(
                g_MtL + (size_t)(bn + lrow) * KTOT + kt + lkg);
            uint4 h0v = pH[0], h1v = pH[1];
            uint4 l0v = pL[0], l1v = pL[1];
            uint32_t* dH = BsH + lrow * LDS_W + (lkg >> 1);
            uint32_t* dL = BsL + lrow * LDS_W + (lkg >> 1);
            dH[0]=h0v.x; dH[1]=h0v.y; dH[2]=h0v.z; dH[3]=h0v.w;
            dH[4]=h1v.x; dH[5]=h1v.y; dH[6]=h1v.z; dH[7]=h1v.w;
            dL[0]=l0v.x; dL[1]=l0v.y; dL[2]=l0v.z; dL[3]=l0v.w;
            dL[4]=l1v.x; dL[5]=l1v.y; dL[6]=l1v.z; dL[7]=l1v.w;
        }
        __syncthreads();

        // ---- compute: 2 k16 steps ----
        #pragma unroll
        for (int ks = 0; ks < 2; ks++) {
            const int kk = ks * 16;
            uint32_t aH[2][4], aL[2][4];
            #pragma unroll
            for (int mt = 0; mt < 2; mt++) {
                uint32_t off = ((warp_m + mt * 16 + a_row) * LDS_W) * 4
                             + (kk + a_k) * 2;
                ldm_x4(aH[mt], asH + off);
                ldm_x4(aL[mt], asL + off);
            }
            #pragma unroll
            for (int ntp = 0; ntp < 4; ntp++) {
                uint32_t bH[4], bL[4];
                uint32_t off = ((warp_n + ntp * 16 + b_row) * LDS_W) * 4
                             + (kk + b_k) * 2;
                ldm_x4(bH, bsH + off);
                ldm_x4(bL, bsL + off);
                #pragma unroll
                for (int mt = 0; mt < 2; mt++) {
                    #pragma unroll
                    for (int j = 0; j < 2; j++) {
                        float* c = acc[mt][ntp * 2 + j];
                        mma_bf16(c, aH[mt], bH[2*j], bH[2*j+1]);
                        mma_bf16(c, aH[mt], bL[2*j], bL[2*j+1]);
                        mma_bf16(c, aL[mt], bH[2*j], bH[2*j+1]);
                    }
                }
            }
        }
        __syncthreads();
    }

    // ---- epilogue ----
    #pragma unroll
    for (int mt = 0; mt < 2; mt++) {
        #pragma unroll
        for (int nt = 0; nt < 8; nt++) {
            int r0  = bm + warp_m + mt * 16 + (lane >> 2);
            int col = bn + warp_n + nt * 8 + (lane & 3) * 2;
            if (r0 < N)
                *reinterpret_cast<float2*>(out + (size_t)r0 * C + col) =
                    make_float2(acc[mt][nt][0], acc[mt][nt][1]);
            int r1 = r0 + 8;
            if (r1 < N)
                *reinterpret_cast<float2*>(out + (size_t)r1 * C + col) =
                    make_float2(acc[mt][nt][2], acc[mt][nt][3]);
        }
    }
}

// ---------------------------------------------------------------------------
// Launch
// ---------------------------------------------------------------------------
extern "C" void kernel_launch(void* const* d_in, const int* in_sizes, int n_in,
                              void* d_out, int out_size) {
    const float* x    = (const float*)d_in[0];
    const float* vals = (const float*)d_in[1];
    const void*  ei   = d_in[2];
    const float* h0   = (const float*)d_in[3];
    const float* W1   = (const float*)d_in[4];
    const float* W2   = (const float*)d_in[5];
    const float* pa   = (const float*)d_in[6];
    const float* pb   = (const float*)d_in[7];
    float* out = (float*)d_out;

    const int N = in_sizes[0] / C;     // 100000
    int E = in_sizes[1];               // 3200000
    if (E > MAXE) E = MAXE;

    // 0) detect int32 vs int64 edge buffer
    detect_idx_kernel<<<1, 32>>>((const int*)ei, in_sizes[2]);

    // 1) build split+transposed blend matrix
    build_Mt_kernel<<<(C * KTOT + 255) / 256, 256>>>(W1, W2, pa, pb);

    // 2) CSR build
    zero_cnt_kernel<<<(N + 255) / 256, 256>>>(N);
    hist_kernel<<<4096, 256>>>(ei, E, N);
    scan_kernel<<<1, 1024>>>(N, E);
    scatter_kernel<<<4096, 256>>>(ei, vals, E, N);

    // 3) SpMM over CSR (one warp per row)
    int spmm_blocks = (N * 32 + 255) / 256;
    spmm_csr_kernel<<<spmm_blocks, 256>>>(x, N);

    // 4) tensor-core GEMM: out = [ax|h0] @ M
    dim3 grid((N + BM - 1) / BM, C / BN);
    gemm_bf16_kernel<<<grid, 256>>>(h0, out, N);
}

// round 5
// speedup vs baseline: 2.3592x; 1.1596x over previous
#include <cuda_runtime.h>
#include <cuda_bf16.h>
#include <cstdint>

#define C 256
#define MAXN 100000
#define MAXE 3200000
#define KTOT 512
#define NCH  8192   // scan chunks

// Scratch (__device__ globals; allocation-free rule)
__device__ __align__(256) __nv_bfloat16 g_axH[(size_t)MAXN * C];
__device__ __align__(256) __nv_bfloat16 g_axL[(size_t)MAXN * C];
__device__ __align__(256) __nv_bfloat16 g_h0H[(size_t)MAXN * C];
__device__ __align__(256) __nv_bfloat16 g_h0L[(size_t)MAXN * C];
__device__ __align__(256) __nv_bfloat16 g_MtH[C * KTOT];   // M^T hi, [n][k]
__device__ __align__(256) __nv_bfloat16 g_MtL[C * KTOT];   // M^T lo, [n][k]
__device__ int   g_is64;
__device__ int   g_cnt[MAXN];
__device__ int   g_rowstart[MAXN + 1];
__device__ int   g_cursor[MAXN];
__device__ int   g_cols[MAXE];
__device__ float g_vals[MAXE];
__device__ int   g_psum[NCH];
__device__ int   g_poff[NCH];

// ---------------------------------------------------------------------------
__device__ __forceinline__ void split_pair(float x, float y,
                                           uint32_t& hi, uint32_t& lo) {
    __nv_bfloat162 h = __floats2bfloat162_rn(x, y);
    float hx = __bfloat162float(__low2bfloat16(h));
    float hy = __bfloat162float(__high2bfloat16(h));
    __nv_bfloat162 l = __floats2bfloat162_rn(x - hx, y - hy);
    hi = *reinterpret_cast<uint32_t*>(&h);
    lo = *reinterpret_cast<uint32_t*>(&l);
}

// ---------------------------------------------------------------------------
__global__ void detect_idx_kernel(const int* __restrict__ ei32, int nwords) {
    if (threadIdx.x != 0 || blockIdx.x != 0) return;
    int nonzero_odd = 0;
    int lim = nwords < 1024 ? nwords : 1024;
    for (int i = 1; i < lim; i += 2) nonzero_odd += (ei32[i] != 0);
    g_is64 = (nonzero_odd == 0) ? 1 : 0;
}

__global__ void zero_cnt_kernel(int N) {
    int i = blockIdx.x * blockDim.x + threadIdx.x;
    if (i < N) g_cnt[i] = 0;
}

// Build transposed+split blend matrix g_Mt[n][k]
__global__ void build_Mt_kernel(const float* __restrict__ W1,
                                const float* __restrict__ W2,
                                const float* __restrict__ p_alpha,
                                const float* __restrict__ p_beta) {
    float a = *p_alpha, b = *p_beta;
    float c1 = (1.f - a) * (1.f - b);
    float c2 = (1.f - a) * b;
    float c3 = a * (1.f - b);
    float c4 = a * b;
    int i = blockIdx.x * blockDim.x + threadIdx.x;
    if (i >= C * KTOT) return;
    int n = i / KTOT, k = i % KTOT;
    float v;
    if (k < C) {
        v = c2 * W1[k * C + n] + (k == n ? c1 : 0.f);
    } else {
        int k2 = k - C;
        v = c4 * W2[k2 * C + n] + (k2 == n ? c3 : 0.f);
    }
    __nv_bfloat16 hi = __float2bfloat16_rn(v);
    g_MtH[i] = hi;
    g_MtL[i] = __float2bfloat16_rn(v - __bfloat162float(hi));
}

// Pre-split h0 into bf16 hi/lo
__global__ void split_h0_kernel(const float* __restrict__ h0, int total4) {
    int i = blockIdx.x * blockDim.x + threadIdx.x;
    if (i >= total4) return;
    float4 v = __ldg(&reinterpret_cast<const float4*>(h0)[i]);
    uint32_t h0w, l0w, h1w, l1w;
    split_pair(v.x, v.y, h0w, l0w);
    split_pair(v.z, v.w, h1w, l1w);
    reinterpret_cast<uint2*>(g_h0H)[i] = make_uint2(h0w, h1w);
    reinterpret_cast<uint2*>(g_h0L)[i] = make_uint2(l0w, l1w);
}

// ---------------------------------------------------------------------------
// CSR build: histogram -> 3-phase scan -> ticket scatter
// ---------------------------------------------------------------------------
__global__ void hist_kernel(const void* __restrict__ ei_raw, int E, int N) {
    const int is64 = g_is64;
    const long long* ei64 = (const long long*)ei_raw;
    const int*       ei32 = (const int*)ei_raw;
    for (int e = blockIdx.x * blockDim.x + threadIdx.x; e < E;
         e += gridDim.x * blockDim.x) {
        int row = is64 ? (int)__ldg(&ei64[e]) : __ldg(&ei32[e]);
        if ((unsigned)row < (unsigned)N) atomicAdd(&g_cnt[row], 1);
    }
}

__global__ void scan_p1(int N) {
    int j = blockIdx.x * blockDim.x + threadIdx.x;
    if (j >= NCH) return;
    int ch = (N + NCH - 1) / NCH;
    int s = j * ch, e = min(s + ch, N);
    int acc = 0;
    for (int i = s; i < e; i++) acc += g_cnt[i];
    g_psum[j] = acc;
}

__global__ void scan_p2() {   // 1 block, 1024 threads, 8 vals/thread
    __shared__ int sh[1024];
    int t = threadIdx.x;
    int loc[8];
    int s = 0;
    #pragma unroll
    for (int k = 0; k < 8; k++) { loc[k] = g_psum[t * 8 + k]; s += loc[k]; }
    sh[t] = s;
    __syncthreads();
    for (int off = 1; off < 1024; off <<= 1) {
        int add = (t >= off) ? sh[t - off] : 0;
        __syncthreads();
        sh[t] += add;
        __syncthreads();
    }
    int run = sh[t] - s;   // exclusive prefix
    #pragma unroll
    for (int k = 0; k < 8; k++) { g_poff[t * 8 + k] = run; run += loc[k]; }
}

__global__ void scan_p3(int N, int E) {
    int j = blockIdx.x * blockDim.x + threadIdx.x;
    if (j >= NCH) return;
    int ch = (N + NCH - 1) / NCH;
    int s = j * ch, e = min(s + ch, N);
    int base = g_poff[j];
    for (int i = s; i < e; i++) {
        int c = g_cnt[i];
        g_rowstart[i] = base;
        g_cursor[i]   = base;
        base += c;
    }
    if (j == 0) g_rowstart[N] = E;
}

__global__ void scatter_kernel(const void* __restrict__ ei_raw,
                               const float* __restrict__ vals, int E, int N) {
    const int is64 = g_is64;
    const long long* ei64 = (const long long*)ei_raw;
    const int*       ei32 = (const int*)ei_raw;
    for (int e = blockIdx.x * blockDim.x + threadIdx.x; e < E;
         e += gridDim.x * blockDim.x) {
        int row, col;
        if (is64) {
            row = (int)__ldg(&ei64[e]);
            col = (int)__ldg(&ei64[(size_t)E + e]);
        } else {
            row = __ldg(&ei32[e]);
            col = __ldg(&ei32[(size_t)E + e]);
        }
        if ((unsigned)row >= (unsigned)N || (unsigned)col >= (unsigned)N) continue;
        int pos = atomicAdd(&g_cursor[row], 1);
        g_cols[pos] = col;
        g_vals[pos] = __ldg(&vals[e]);
    }
}

// ---------------------------------------------------------------------------
// SpMM over CSR: one warp per row; 2-edge unrolled; epilogue stores bf16 hi/lo
// ---------------------------------------------------------------------------
__global__ __launch_bounds__(256)
void spmm_csr_kernel(const float* __restrict__ x, int N) {
    int warp = (blockIdx.x * blockDim.x + threadIdx.x) >> 5;
    int lane = threadIdx.x & 31;
    int nw   = (gridDim.x * blockDim.x) >> 5;
    for (int r = warp; r < N; r += nw) {
        int s = g_rowstart[r];
        int e = g_rowstart[r + 1];
        float4 acc0 = make_float4(0.f, 0.f, 0.f, 0.f);
        float4 acc1 = make_float4(0.f, 0.f, 0.f, 0.f);
        int i = s;
        for (; i + 2 <= e; i += 2) {
            int c0 = __ldg(&g_cols[i]);
            int c1 = __ldg(&g_cols[i + 1]);
            float v0 = __ldg(&g_vals[i]);
            float v1 = __ldg(&g_vals[i + 1]);
            const float4* x0 = reinterpret_cast<const float4*>(x + (size_t)c0 * C);
            const float4* x1 = reinterpret_cast<const float4*>(x + (size_t)c1 * C);
            float4 a0 = __ldg(&x0[lane]);
            float4 b0 = __ldg(&x0[lane + 32]);
            float4 a1 = __ldg(&x1[lane]);
            float4 b1 = __ldg(&x1[lane + 32]);
            acc0.x += v0 * a0.x + v1 * a1.x;
            acc0.y += v0 * a0.y + v1 * a1.y;
            acc0.z += v0 * a0.z + v1 * a1.z;
            acc0.w += v0 * a0.w + v1 * a1.w;
            acc1.x += v0 * b0.x + v1 * b1.x;
            acc1.y += v0 * b0.y + v1 * b1.y;
            acc1.z += v0 * b0.z + v1 * b1.z;
            acc1.w += v0 * b0.w + v1 * b1.w;
        }
        if (i < e) {
            int c0 = __ldg(&g_cols[i]);
            float v0 = __ldg(&g_vals[i]);
            const float4* x0 = reinterpret_cast<const float4*>(x + (size_t)c0 * C);
            float4 a0 = __ldg(&x0[lane]);
            float4 b0 = __ldg(&x0[lane + 32]);
            acc0.x += v0 * a0.x; acc0.y += v0 * a0.y;
            acc0.z += v0 * a0.z; acc0.w += v0 * a0.w;
            acc1.x += v0 * b0.x; acc1.y += v0 * b0.y;
            acc1.z += v0 * b0.z; acc1.w += v0 * b0.w;
        }
        // split + streaming store (identical bits to in-loader split)
        uint32_t h0w, l0w, h1w, l1w;
        split_pair(acc0.x, acc0.y, h0w, l0w);
        split_pair(acc0.z, acc0.w, h1w, l1w);
        uint2* dH = reinterpret_cast<uint2*>(g_axH + (size_t)r * C + lane * 4);
        uint2* dL = reinterpret_cast<uint2*>(g_axL + (size_t)r * C + lane * 4);
        __stcs(dH, make_uint2(h0w, h1w));
        __stcs(dL, make_uint2(l0w, l1w));
        split_pair(acc1.x, acc1.y, h0w, l0w);
        split_pair(acc1.z, acc1.w, h1w, l1w);
        dH = reinterpret_cast<uint2*>(g_axH + (size_t)r * C + 128 + lane * 4);
        dL = reinterpret_cast<uint2*>(g_axL + (size_t)r * C + 128 + lane * 4);
        __stcs(dH, make_uint2(h0w, h1w));
        __stcs(dL, make_uint2(l0w, l1w));
    }
}

// ---------------------------------------------------------------------------
// Tensor-core GEMM: out[N,256] = [ax|h0] @ M, bf16 hi/lo (fp32-accurate)
// 2-stage cp.async pipeline, pure-copy loaders, 128x128 tile, BK=32.
// ---------------------------------------------------------------------------
#define BM 128
#define BN 128
#define BK 32
#define LDS_W 20                     // words/row: 16 data + 4 pad
#define ARR_W (128 * LDS_W)          // 2560 words per array
#define STG_W (4 * ARR_W)            // words per stage
#define SMEM_BYTES (2 * STG_W * 4)   // 81920

__device__ __forceinline__ uint32_t s2u(const void* p) {
    uint32_t a;
    asm("{ .reg .u64 t; cvta.to.shared.u64 t, %1; cvt.u32.u64 %0, t; }"
        : "=r"(a) : "l"(p));
    return a;
}
__device__ __forceinline__ void cp16(uint32_t daddr, const void* g) {
    asm volatile("cp.async.cg.shared.global [%0], [%1], 16;"
                 :: "r"(daddr), "l"(g));
}
__device__ __forceinline__ void cp16z(uint32_t daddr, const void* g) {
    asm volatile("cp.async.cg.shared.global [%0], [%1], 16, 0;"
                 :: "r"(daddr), "l"(g));
}
__device__ __forceinline__ void cp_commit() {
    asm volatile("cp.async.commit_group;");
}
__device__ __forceinline__ void cp_wait0() {
    asm volatile("cp.async.wait_group 0;");
}
__device__ __forceinline__ void ldm_x4(uint32_t* r, uint32_t addr) {
    asm volatile("ldmatrix.sync.aligned.m8n8.x4.shared.b16 {%0,%1,%2,%3}, [%4];"
                 : "=r"(r[0]), "=r"(r[1]), "=r"(r[2]), "=r"(r[3]) : "r"(addr));
}
__device__ __forceinline__ void mma_bf16(float* c, const uint32_t* a,
                                         uint32_t b0, uint32_t b1) {
    asm volatile(
        "mma.sync.aligned.m16n8k16.row.col.f32.bf16.bf16.f32 "
        "{%0,%1,%2,%3}, {%4,%5,%6,%7}, {%8,%9}, {%0,%1,%2,%3};"
        : "+f"(c[0]), "+f"(c[1]), "+f"(c[2]), "+f"(c[3])
        : "r"(a[0]), "r"(a[1]), "r"(a[2]), "r"(a[3]), "r"(b0), "r"(b1));
}

__global__ __launch_bounds__(256, 2)
void gemm_bf16_kernel(float* __restrict__ out, int N) {
    extern __shared__ uint32_t smem[];
    const uint32_t sbase = s2u(smem);

    const int tid  = threadIdx.x;
    const int lane = tid & 31;
    const int wid  = tid >> 5;
    const int warp_m = (wid & 3) * 32;
    const int warp_n = (wid >> 2) * 64;
    const int bn = blockIdx.x * BN;       // x = bn so bm-neighbors co-run
    const int bm = blockIdx.y * BM;

    const int a_row = (lane & 7) + ((lane >> 3) & 1) * 8;
    const int a_k   = (lane >> 4) * 8;
    const int b_row = (lane & 7) + (lane >> 4) * 8;
    const int b_k   = ((lane >> 3) & 1) * 8;

    float acc[2][8][4];
    #pragma unroll
    for (int i = 0; i < 2; i++)
        #pragma unroll
        for (int j = 0; j < 8; j++)
            #pragma unroll
            for (int q = 0; q < 4; q++) acc[i][j][q] = 0.f;

    // loader mapping: thread -> (row, k-half)
    const int lrow = tid >> 1;
    const int lh   = tid & 1;          // 16-bf16 half of the 32-wide tile
    const int arow = bm + lrow;
    const bool avalid = (arow < N);
    const int acl = avalid ? arow : 0;

    const int T = KTOT / BK;           // 16 tiles

    // ---- stage loader (pure copies) ----
    auto load_tile = [&](int t, int stg) {
        const int kt = t * BK;
        const size_t aoff = (size_t)acl * C + ((kt < C) ? kt : kt - C) + lh * 16;
        const __nv_bfloat16* gAH = (kt < C) ? (g_axH + aoff) : (g_h0H + aoff);
        const __nv_bfloat16* gAL = (kt < C) ? (g_axL + aoff) : (g_h0L + aoff);
        const size_t boff = (size_t)(bn + lrow) * KTOT + kt + lh * 16;
        const __nv_bfloat16* gBH = g_MtH + boff;
        const __nv_bfloat16* gBL = g_MtL + boff;
        uint32_t drow = sbase + (stg * STG_W + lrow * LDS_W + lh * 8) * 4;
        #pragma unroll
        for (int c = 0; c < 2; c++) {
            if (avalid) {
                cp16(drow + c * 16,               gAH + c * 8);
                cp16(drow + ARR_W * 4 + c * 16,   gAL + c * 8);
            } else {
                cp16z(drow + c * 16,              gAH + c * 8);
                cp16z(drow + ARR_W * 4 + c * 16,  gAL + c * 8);
            }
            cp16(drow + 2 * ARR_W * 4 + c * 16,   gBH + c * 8);
            cp16(drow + 3 * ARR_W * 4 + c * 16,   gBL + c * 8);
        }
        cp_commit();
    };

    load_tile(0, 0);

    for (int t = 0; t < T; t++) {
        cp_wait0();
        __syncthreads();
        if (t + 1 < T) load_tile(t + 1, (t + 1) & 1);

        const int stg = t & 1;
        const uint32_t aH0 = sbase + (stg * STG_W) * 4;
        const uint32_t aL0 = aH0 + ARR_W * 4;
        const uint32_t bH0 = aH0 + 2 * ARR_W * 4;
        const uint32_t bL0 = aH0 + 3 * ARR_W * 4;

        #pragma unroll
        for (int ks = 0; ks < 2; ks++) {
            const int kk = ks * 16;
            uint32_t aH[2][4], aL[2][4];
            #pragma unroll
            for (int mt = 0; mt < 2; mt++) {
                uint32_t off = ((warp_m + mt * 16 + a_row) * LDS_W) * 4
                             + (kk + a_k) * 2;
                ldm_x4(aH[mt], aH0 + off);
                ldm_x4(aL[mt], aL0 + off);
            }
            #pragma unroll
            for (int ntp = 0; ntp < 4; ntp++) {
                uint32_t bH[4], bL[4];
                uint32_t off = ((warp_n + ntp * 16 + b_row) * LDS_W) * 4
                             + (kk + b_k) * 2;
                ldm_x4(bH, bH0 + off);
                ldm_x4(bL, bL0 + off);
                #pragma unroll
                for (int mt = 0; mt < 2; mt++) {
                    #pragma unroll
                    for (int j = 0; j < 2; j++) {
                        float* c = acc[mt][ntp * 2 + j];
                        mma_bf16(c, aH[mt], bH[2*j], bH[2*j+1]);
                        mma_bf16(c, aH[mt], bL[2*j], bL[2*j+1]);
                        mma_bf16(c, aL[mt], bH[2*j], bH[2*j+1]);
                    }
                }
            }
        }
        __syncthreads();
    }

    // ---- epilogue ----
    #pragma unroll
    for (int mt = 0; mt < 2; mt++) {
        #pragma unroll
        for (int nt = 0; nt < 8; nt++) {
            int r0  = bm + warp_m + mt * 16 + (lane >> 2);
            int col = bn + warp_n + nt * 8 + (lane & 3) * 2;
            if (r0 < N)
                *reinterpret_cast<float2*>(out + (size_t)r0 * C + col) =
                    make_float2(acc[mt][nt][0], acc[mt][nt][1]);
            int r1 = r0 + 8;
            if (r1 < N)
                *reinterpret_cast<float2*>(out + (size_t)r1 * C + col) =
                    make_float2(acc[mt][nt][2], acc[mt][nt][3]);
        }
    }
}

// ---------------------------------------------------------------------------
// Launch
// ---------------------------------------------------------------------------
extern "C" void kernel_launch(void* const* d_in, const int* in_sizes, int n_in,
                              void* d_out, int out_size) {
    const float* x    = (const float*)d_in[0];
    const float* vals = (const float*)d_in[1];
    const void*  ei   = d_in[2];
    const float* h0   = (const float*)d_in[3];
    const float* W1   = (const float*)d_in[4];
    const float* W2   = (const float*)d_in[5];
    const float* pa   = (const float*)d_in[6];
    const float* pb   = (const float*)d_in[7];
    float* out = (float*)d_out;

    const int N = in_sizes[0] / C;     // 100000
    int E = in_sizes[1];               // 3200000
    if (E > MAXE) E = MAXE;

    cudaFuncSetAttribute(gemm_bf16_kernel,
                         cudaFuncAttributeMaxDynamicSharedMemorySize, SMEM_BYTES);

    // 0) detect int32 vs int64 edge buffer
    detect_idx_kernel<<<1, 32>>>((const int*)ei, in_sizes[2]);

    // 1) build split+transposed blend matrix; pre-split h0
    build_Mt_kernel<<<(C * KTOT + 255) / 256, 256>>>(W1, W2, pa, pb);
    int total4 = N * C / 4;
    split_h0_kernel<<<(total4 + 255) / 256, 256>>>(h0, total4);

    // 2) CSR build
    zero_cnt_kernel<<<(N + 255) / 256, 256>>>(N);
    hist_kernel<<<4096, 256>>>(ei, E, N);
    scan_p1<<<NCH / 256, 256>>>(N);
    scan_p2<<<1, 1024>>>();
    scan_p3<<<NCH / 256, 256>>>(N, E);
    scatter_kernel<<<4096, 256>>>(ei, vals, E, N);

    // 3) SpMM over CSR (one warp per row) -> writes pre-split bf16 ax
    int spmm_blocks = (N * 32 + 255) / 256;
    spmm_csr_kernel<<<spmm_blocks, 256>>>(x, N);

    // 4) tensor-core GEMM: out = [ax|h0] @ M
    dim3 grid(C / BN, (N + BM - 1) / BM);
    gemm_bf16_kernel<<<grid, 256, SMEM_BYTES>>>(out, N);
}